// round 1
// baseline (speedup 1.0000x reference)
#include <cuda_runtime.h>

#define N_NODES 20000
#define N_EDGES 10000
#define IN_CH   128
#define OUT_CH  64

// Scratch (device globals — no allocation in kernel_launch).
__device__ float g_xw[N_NODES * OUT_CH];   // x @ theta           [N, 64]
__device__ float g_ef[N_EDGES * OUT_CH];   // edge features       [E, 64]

// ---------------------------------------------------------------------------
// Kernel 1: g_xw = x @ theta.   x:[N,128], theta:[128,64]
// Block: 128 threads, 32 output rows x 64 cols. Microtile 2x8 per thread.
// ---------------------------------------------------------------------------
__global__ __launch_bounds__(128) void k_xw(const float* __restrict__ x,
                                            const float* __restrict__ theta) {
    __shared__ float a_s[32][33];   // x^T tile: [k][n], padded
    __shared__ float b_s[32][64];   // theta tile: [k][c]
    const int tid = threadIdx.x;
    const int rg  = tid >> 3;       // 0..15 -> 2 rows each
    const int cg  = tid & 7;        // 0..7  -> 8 cols each
    const int n0  = blockIdx.x * 32;

    float acc[2][8];
#pragma unroll
    for (int i = 0; i < 2; i++)
#pragma unroll
        for (int j = 0; j < 8; j++) acc[i][j] = 0.f;

    for (int k0 = 0; k0 < IN_CH; k0 += 32) {
        // A: x[n0+i][k0+j] -> a_s[j][i]  (transpose into smem)
#pragma unroll
        for (int t = 0; t < 8; t++) {
            int idx = tid + t * 128;
            int i = idx >> 5, j = idx & 31;
            a_s[j][i] = x[(n0 + i) * IN_CH + k0 + j];
        }
        // B: theta[k0+r][c] -> b_s[r][c]
#pragma unroll
        for (int t = 0; t < 4; t++) {
            int idx4 = tid + t * 128;
            int r = idx4 >> 4, c4 = idx4 & 15;
            ((float4*)b_s[r])[c4] = ((const float4*)(theta + (k0 + r) * OUT_CH))[c4];
        }
        __syncthreads();
#pragma unroll
        for (int k = 0; k < 32; k++) {
            float a0 = a_s[k][rg * 2 + 0];
            float a1 = a_s[k][rg * 2 + 1];
            float4 b0 = *(float4*)&b_s[k][cg * 8 + 0];
            float4 b1 = *(float4*)&b_s[k][cg * 8 + 4];
            float bb[8] = {b0.x, b0.y, b0.z, b0.w, b1.x, b1.y, b1.z, b1.w};
#pragma unroll
            for (int j = 0; j < 8; j++) {
                acc[0][j] += a0 * bb[j];
                acc[1][j] += a1 * bb[j];
            }
        }
        __syncthreads();
    }
#pragma unroll
    for (int i = 0; i < 2; i++) {
        int n = n0 + rg * 2 + i;
        float4 o0 = make_float4(acc[i][0], acc[i][1], acc[i][2], acc[i][3]);
        float4 o1 = make_float4(acc[i][4], acc[i][5], acc[i][6], acc[i][7]);
        *(float4*)&g_xw[n * OUT_CH + cg * 8 + 0] = o0;
        *(float4*)&g_xw[n * OUT_CH + cg * 8 + 4] = o1;
    }
}

// ---------------------------------------------------------------------------
// Kernel 2: g_ef[e][c] = (sum_n H[n][e] * g_xw[n][c]) / de[e],
//           de[e] = sum_n H[n][e]   (computed inline — block owns all n).
// Block: 128 threads, 32 e x 64 c tile, K-loop over all N. Grid: ceil(E/32).
// ---------------------------------------------------------------------------
__global__ __launch_bounds__(128) void k_edge(const float* __restrict__ H) {
    __shared__ float a_s[32][32];   // [k=n][e]  (H slab, already k-major)
    __shared__ float b_s[32][64];   // [k=n][c]  (xw slab)
    const int tid = threadIdx.x;
    const int eg  = tid >> 3;       // 0..15 -> 2 e's each
    const int cg  = tid & 7;        // 0..7  -> 8 c's each
    const int e0  = blockIdx.x * 32;

    float acc[2][8];
#pragma unroll
    for (int i = 0; i < 2; i++)
#pragma unroll
        for (int j = 0; j < 8; j++) acc[i][j] = 0.f;
    float de0 = 0.f, de1 = 0.f;

    for (int n0 = 0; n0 < N_NODES; n0 += 32) {
        // A: H[n0+i][e0+j] -> a_s[i][j]
#pragma unroll
        for (int t = 0; t < 8; t++) {
            int idx = tid + t * 128;
            int i = idx >> 5, j = idx & 31;
            int e = e0 + j;
            a_s[i][j] = (e < N_EDGES) ? H[(long)(n0 + i) * N_EDGES + e] : 0.f;
        }
        // B: g_xw[n0+r][c] -> b_s[r][c]
#pragma unroll
        for (int t = 0; t < 4; t++) {
            int idx4 = tid + t * 128;
            int r = idx4 >> 4, c4 = idx4 & 15;
            ((float4*)b_s[r])[c4] = ((const float4*)(g_xw + (n0 + r) * OUT_CH))[c4];
        }
        __syncthreads();
#pragma unroll
        for (int k = 0; k < 32; k++) {
            float a0 = a_s[k][eg * 2 + 0];
            float a1 = a_s[k][eg * 2 + 1];
            float4 b0 = *(float4*)&b_s[k][cg * 8 + 0];
            float4 b1 = *(float4*)&b_s[k][cg * 8 + 4];
            de0 += a0;
            de1 += a1;
            float bb[8] = {b0.x, b0.y, b0.z, b0.w, b1.x, b1.y, b1.z, b1.w};
#pragma unroll
            for (int j = 0; j < 8; j++) {
                acc[0][j] += a0 * bb[j];
                acc[1][j] += a1 * bb[j];
            }
        }
        __syncthreads();
    }
    float inv0 = 1.f / de0;
    float inv1 = 1.f / de1;
#pragma unroll
    for (int i = 0; i < 2; i++) {
        int e = e0 + eg * 2 + i;
        if (e < N_EDGES) {
            float inv = (i == 0) ? inv0 : inv1;
            float4 o0 = make_float4(acc[i][0] * inv, acc[i][1] * inv,
                                    acc[i][2] * inv, acc[i][3] * inv);
            float4 o1 = make_float4(acc[i][4] * inv, acc[i][5] * inv,
                                    acc[i][6] * inv, acc[i][7] * inv);
            *(float4*)&g_ef[e * OUT_CH + cg * 8 + 0] = o0;
            *(float4*)&g_ef[e * OUT_CH + cg * 8 + 4] = o1;
        }
    }
}

// ---------------------------------------------------------------------------
// Kernel 3: out[n][c] = (sum_e H[n][e] * g_ef[e][c]) / dn[n],
//           dn[n] = sum_e H[n][e]   (computed inline — block owns all e).
// Block: 128 threads, 32 n x 64 c tile, K-loop over all E. Grid: N/32 = 625.
// ---------------------------------------------------------------------------
__global__ __launch_bounds__(128) void k_node(const float* __restrict__ H,
                                              float* __restrict__ out) {
    __shared__ float a_s[32][33];   // [k=e][n]  transposed, padded
    __shared__ float b_s[32][64];   // [k=e][c]  edge-feature slab
    const int tid = threadIdx.x;
    const int ng  = tid >> 3;       // 0..15 -> 2 n's each
    const int cg  = tid & 7;        // 0..7  -> 8 c's each
    const int n0  = blockIdx.x * 32;

    float acc[2][8];
#pragma unroll
    for (int i = 0; i < 2; i++)
#pragma unroll
        for (int j = 0; j < 8; j++) acc[i][j] = 0.f;
    float dn0 = 0.f, dn1 = 0.f;

    for (int e0 = 0; e0 < N_EDGES; e0 += 32) {
        // A: H[n0+i][e0+j] -> a_s[j][i]  (transpose; pad kills STS conflicts)
#pragma unroll
        for (int t = 0; t < 8; t++) {
            int idx = tid + t * 128;
            int i = idx >> 5, j = idx & 31;
            int e = e0 + j;
            a_s[j][i] = (e < N_EDGES) ? H[(long)(n0 + i) * N_EDGES + e] : 0.f;
        }
        // B: g_ef[e0+r][c] -> b_s[r][c]
#pragma unroll
        for (int t = 0; t < 4; t++) {
            int idx4 = tid + t * 128;
            int r = idx4 >> 4, c4 = idx4 & 15;
            int e = e0 + r;
            float4 v = make_float4(0.f, 0.f, 0.f, 0.f);
            if (e < N_EDGES) v = ((const float4*)(g_ef + e * OUT_CH))[c4];
            ((float4*)b_s[r])[c4] = v;
        }
        __syncthreads();
#pragma unroll
        for (int k = 0; k < 32; k++) {
            float a0 = a_s[k][ng * 2 + 0];
            float a1 = a_s[k][ng * 2 + 1];
            float4 b0 = *(float4*)&b_s[k][cg * 8 + 0];
            float4 b1 = *(float4*)&b_s[k][cg * 8 + 4];
            dn0 += a0;
            dn1 += a1;
            float bb[8] = {b0.x, b0.y, b0.z, b0.w, b1.x, b1.y, b1.z, b1.w};
#pragma unroll
            for (int j = 0; j < 8; j++) {
                acc[0][j] += a0 * bb[j];
                acc[1][j] += a1 * bb[j];
            }
        }
        __syncthreads();
    }
    float inv0 = 1.f / dn0;
    float inv1 = 1.f / dn1;
#pragma unroll
    for (int i = 0; i < 2; i++) {
        int n = n0 + ng * 2 + i;
        float inv = (i == 0) ? inv0 : inv1;
        float4 o0 = make_float4(acc[i][0] * inv, acc[i][1] * inv,
                                acc[i][2] * inv, acc[i][3] * inv);
        float4 o1 = make_float4(acc[i][4] * inv, acc[i][5] * inv,
                                acc[i][6] * inv, acc[i][7] * inv);
        *(float4*)&out[n * OUT_CH + cg * 8 + 0] = o0;
        *(float4*)&out[n * OUT_CH + cg * 8 + 4] = o1;
    }
}

// ---------------------------------------------------------------------------
extern "C" void kernel_launch(void* const* d_in, const int* in_sizes, int n_in,
                              void* d_out, int out_size) {
    const float* x     = (const float*)d_in[0];   // [20000, 128]
    const float* H     = (const float*)d_in[1];   // [20000, 10000]
    const float* theta = (const float*)d_in[2];   // [128, 64]
    float* out         = (float*)d_out;           // [20000, 64]

    k_xw<<<N_NODES / 32, 128>>>(x, theta);
    k_edge<<<(N_EDGES + 31) / 32, 128>>>(H);
    k_node<<<N_NODES / 32, 128>>>(H, out);
    (void)in_sizes; (void)n_in; (void)out_size;
}